// round 3
// baseline (speedup 1.0000x reference)
#include <cuda_runtime.h>
#include <cuda_bf16.h>
#include <math.h>

// ============================================================================
// LocalAttention: cntx, attn = softmax(mask ? -1e9 : (xWq^T)(xWk^T)^T/sqrt(D)) @ (xWv^T)
// N=8192, D=512, fp32.  Output layout: [cntx (N*D) | attn (N*N)].
// Mask arrives as int32 (bool coerced by harness).
// ============================================================================

#define AN 8192
#define AD 512

// Scratch for Q, K, V projections (device globals: allocation-free rule).
__device__ float g_Q[(size_t)AN * AD];
__device__ float g_K[(size_t)AN * AD];
__device__ float g_V[(size_t)AN * AD];
// Fallback scores scratch in case d_out only holds cntx.
__device__ float g_S[(size_t)AN * (size_t)AN];

// Packed dual-FMA (Blackwell f32x2 pipe; ptxas only emits FFMA2 from this PTX).
__device__ __forceinline__ float2 ffma2(float2 a, float2 b, float2 c) {
    float2 d;
    asm("fma.rn.f32x2 %0, %1, %2, %3;"
        : "=l"(*reinterpret_cast<unsigned long long*>(&d))
        : "l"(*reinterpret_cast<const unsigned long long*>(&a)),
          "l"(*reinterpret_cast<const unsigned long long*>(&b)),
          "l"(*reinterpret_cast<const unsigned long long*>(&c)));
    return d;
}

// ----------------------------------------------------------------------------
// Tiled GEMM.
//   BT=true : C[M,Nn] = A[M,K] * B[Nn,K]^T   (both K-contiguous, "NT")
//   BT=false: C[M,Nn] = A[M,K] * B[K,Nn]     ("NN")
//   MASK_EPI: C = mask ? -1e9 : C*scale  (mask is [M,Nn] int32)
// Block tile: BM=TM*16 x BN=128 x BK=16, 256 threads, thread tile TM x 8.
// ----------------------------------------------------------------------------
template <int TM, bool BT, bool MASK_EPI>
__global__ __launch_bounds__(256)
void gemm_kernel(const float* __restrict__ A, const float* __restrict__ B,
                 float* __restrict__ C, int M, int Nn, int K,
                 const int* __restrict__ mask, float scale)
{
    constexpr int BM = TM * 16;
    constexpr int BN = 128;
    constexpr int BK = 16;

    __shared__ float As[BK][BM];
    __shared__ float Bs[BK][BN];

    const int tid = threadIdx.x;
    const int tx = tid & 15;        // 0..15 -> 8 cols each
    const int ty = tid >> 4;        // 0..15 -> TM rows each
    const int mBase = blockIdx.y * BM;
    const int nBase = blockIdx.x * BN;

    float2 acc[TM][4];
#pragma unroll
    for (int i = 0; i < TM; i++)
#pragma unroll
        for (int j = 0; j < 4; j++) acc[i][j] = make_float2(0.f, 0.f);

    constexpr int A_F4 = BM * BK / 4;   // float4 loads for A tile
    constexpr int B_F4 = BN * BK / 4;   // float4 loads for B tile

    for (int k0 = 0; k0 < K; k0 += BK) {
        // --- A tile: BM rows x BK cols, store transposed As[k][m] ---
#pragma unroll
        for (int t = tid; t < A_F4; t += 256) {
            int rr = t >> 2, c4 = t & 3;
            float4 v = *(const float4*)(A + (size_t)(mBase + rr) * K + k0 + c4 * 4);
            As[c4 * 4 + 0][rr] = v.x;
            As[c4 * 4 + 1][rr] = v.y;
            As[c4 * 4 + 2][rr] = v.z;
            As[c4 * 4 + 3][rr] = v.w;
        }
        // --- B tile ---
        if (BT) {
#pragma unroll
            for (int t = tid; t < B_F4; t += 256) {
                int rr = t >> 2, c4 = t & 3;
                float4 v = *(const float4*)(B + (size_t)(nBase + rr) * K + k0 + c4 * 4);
                Bs[c4 * 4 + 0][rr] = v.x;
                Bs[c4 * 4 + 1][rr] = v.y;
                Bs[c4 * 4 + 2][rr] = v.z;
                Bs[c4 * 4 + 3][rr] = v.w;
            }
        } else {
#pragma unroll
            for (int t = tid; t < B_F4; t += 256) {
                int rr = t >> 5, c4 = t & 31;
                *(float4*)&Bs[rr][c4 * 4] =
                    *(const float4*)(B + (size_t)(k0 + rr) * Nn + nBase + c4 * 4);
            }
        }
        __syncthreads();

#pragma unroll
        for (int kk = 0; kk < BK; ++kk) {
            float a[TM];
#pragma unroll
            for (int i = 0; i < TM / 4; i++) {
                float4 av = *(float4*)&As[kk][ty * TM + i * 4];
                a[i * 4 + 0] = av.x; a[i * 4 + 1] = av.y;
                a[i * 4 + 2] = av.z; a[i * 4 + 3] = av.w;
            }
            float4 b0 = *(float4*)&Bs[kk][tx * 8];
            float4 b1 = *(float4*)&Bs[kk][tx * 8 + 4];
            float2 b[4] = { make_float2(b0.x, b0.y), make_float2(b0.z, b0.w),
                            make_float2(b1.x, b1.y), make_float2(b1.z, b1.w) };
#pragma unroll
            for (int i = 0; i < TM; i++) {
                float2 ad = make_float2(a[i], a[i]);
#pragma unroll
                for (int j = 0; j < 4; j++)
                    acc[i][j] = ffma2(ad, b[j], acc[i][j]);
            }
        }
        __syncthreads();
    }

    // --- Epilogue ---
#pragma unroll
    for (int i = 0; i < TM; i++) {
        int m = mBase + ty * TM + i;
        float o[8] = { acc[i][0].x, acc[i][0].y, acc[i][1].x, acc[i][1].y,
                       acc[i][2].x, acc[i][2].y, acc[i][3].x, acc[i][3].y };
        size_t cbase = (size_t)m * Nn + nBase + tx * 8;
        if (MASK_EPI) {
            const int* mp = mask + (size_t)m * Nn + nBase + tx * 8;
            int4 m0 = *(const int4*)(mp);
            int4 m1 = *(const int4*)(mp + 4);
            int mv[8] = { m0.x, m0.y, m0.z, m0.w, m1.x, m1.y, m1.z, m1.w };
#pragma unroll
            for (int j = 0; j < 8; j++)
                o[j] = mv[j] ? -1e9f : o[j] * scale;
        }
        *(float4*)(C + cbase)     = make_float4(o[0], o[1], o[2], o[3]);
        *(float4*)(C + cbase + 4) = make_float4(o[4], o[5], o[6], o[7]);
    }
}

// ----------------------------------------------------------------------------
// Row softmax, in place. One block per row; row (8192 f32 = 32KB) staged in smem.
// ----------------------------------------------------------------------------
__global__ __launch_bounds__(256)
void softmax_rows(float* __restrict__ S, int n)
{
    extern __shared__ float row[];
    __shared__ float red[33];

    const int tid = threadIdx.x;
    float* p = S + (size_t)blockIdx.x * n;

    // load + max
    float m = -INFINITY;
    for (int i = tid * 4; i < n; i += 1024) {
        float4 v = *(const float4*)(p + i);
        *(float4*)(row + i) = v;
        m = fmaxf(m, fmaxf(fmaxf(v.x, v.y), fmaxf(v.z, v.w)));
    }
#pragma unroll
    for (int o = 16; o; o >>= 1) m = fmaxf(m, __shfl_xor_sync(~0u, m, o));
    if ((tid & 31) == 0) red[tid >> 5] = m;
    __syncthreads();
    if (tid < 32) {
        float v = (tid < 8) ? red[tid] : -INFINITY;
#pragma unroll
        for (int o = 4; o; o >>= 1) v = fmaxf(v, __shfl_xor_sync(~0u, v, o));
        if (tid == 0) red[32] = v;
    }
    __syncthreads();
    m = red[32];

    // exp + sum
    float s = 0.f;
    for (int i = tid * 4; i < n; i += 1024) {
        float4 v = *(float4*)(row + i);
        v.x = __expf(v.x - m); v.y = __expf(v.y - m);
        v.z = __expf(v.z - m); v.w = __expf(v.w - m);
        s += (v.x + v.y) + (v.z + v.w);
        *(float4*)(row + i) = v;
    }
    __syncthreads();
#pragma unroll
    for (int o = 16; o; o >>= 1) s += __shfl_xor_sync(~0u, s, o);
    if ((tid & 31) == 0) red[tid >> 5] = s;
    __syncthreads();
    if (tid < 32) {
        float v = (tid < 8) ? red[tid] : 0.f;
#pragma unroll
        for (int o = 4; o; o >>= 1) v += __shfl_xor_sync(~0u, v, o);
        if (tid == 0) red[32] = v;
    }
    __syncthreads();
    const float inv = 1.f / red[32];

    for (int i = tid * 4; i < n; i += 1024) {
        float4 v = *(float4*)(row + i);
        v.x *= inv; v.y *= inv; v.z *= inv; v.w *= inv;
        *(float4*)(p + i) = v;
    }
}

// ----------------------------------------------------------------------------
// Launch
// ----------------------------------------------------------------------------
extern "C" void kernel_launch(void* const* d_in, const int* in_sizes, int n_in,
                              void* d_out, int out_size)
{
    const float* x    = (const float*)d_in[0];
    const int*   mask = (const int*)d_in[1];
    const float* Wq   = (const float*)d_in[2];
    const float* Wk   = (const float*)d_in[3];
    const float* Wv   = (const float*)d_in[4];
    float* out = (float*)d_out;

    float *Qp, *Kp, *Vp;
    cudaGetSymbolAddress((void**)&Qp, g_Q);
    cudaGetSymbolAddress((void**)&Kp, g_K);
    cudaGetSymbolAddress((void**)&Vp, g_V);

    const size_t nd = (size_t)AN * AD;
    const size_t nn = (size_t)AN * AN;
    float* cntx = out;
    float* attn = out + nd;
    if ((size_t)out_size < nd + nn) {   // output holds cntx only -> use scratch
        cudaGetSymbolAddress((void**)&attn, g_S);
    }

    const float scale = 1.0f / sqrtf((float)AD);

    // QKV projections: [8192,512] = x[8192,512] @ W[512,512]^T  (NT)
    dim3 gQKV(AD / 128, AN / 64);
    gemm_kernel<4, true, false><<<gQKV, 256>>>(x, Wq, Qp, AN, AD, AD, nullptr, 1.f);
    gemm_kernel<4, true, false><<<gQKV, 256>>>(x, Wk, Kp, AN, AD, AD, nullptr, 1.f);
    gemm_kernel<4, true, false><<<gQKV, 256>>>(x, Wv, Vp, AN, AD, AD, nullptr, 1.f);

    // Scores: attn = mask ? -1e9 : (Q @ K^T) * scale   (NT, masked epilogue)
    dim3 gS(AN / 128, AN / 128);
    gemm_kernel<8, true, true><<<gS, 256>>>(Qp, Kp, attn, AN, AN, AD, mask, scale);

    // Row softmax in place
    softmax_rows<<<AN, 256, AN * sizeof(float)>>>(attn, AN);

    // Context: cntx = attn[8192,8192] @ V[8192,512]   (NN)
    dim3 gAV(AD / 128, AN / 64);
    gemm_kernel<4, false, false><<<gAV, 256>>>(attn, Vp, cntx, AN, AD, AN, nullptr, 1.f);
}

// round 8
// speedup vs baseline: 3.5213x; 3.5213x over previous
#include <cuda_runtime.h>
#include <cuda_bf16.h>
#include <math.h>
#include <stdint.h>

// ============================================================================
// LocalAttention via split-bf16 warp-level MMA (mma.sync m16n8k16, sm_80 ISA —
// tcgen05 is unavailable: harness compiles for plain sm_103).
//   split x,W -> hi/lo bf16
//   Q = x@Wq^T, K = x@Wk^T, Vt = Wv@x^T      (NT GEMM, split epilogue)
//   attn = softmax(mask ? -1e9 : Q@K^T * s)   (NT GEMM, mask epi; fp32)
//   softmax also emits P hi/lo bf16
//   cntx = P @ Vt^T                           (NT GEMM, fp32 epi)
// Output: [cntx (N*D) | attn (N*N)].  Mask is int32.
// ============================================================================

#define AN 8192
#define AD 512

// ---- device-global scratch (allocation-free rule) ----
__device__ __nv_bfloat16 g_xh [(size_t)AN * AD], g_xl [(size_t)AN * AD];
__device__ __nv_bfloat16 g_Wqh[(size_t)AD * AD], g_Wql[(size_t)AD * AD];
__device__ __nv_bfloat16 g_Wkh[(size_t)AD * AD], g_Wkl[(size_t)AD * AD];
__device__ __nv_bfloat16 g_Wvh[(size_t)AD * AD], g_Wvl[(size_t)AD * AD];
__device__ __nv_bfloat16 g_Qh [(size_t)AN * AD], g_Ql [(size_t)AN * AD];
__device__ __nv_bfloat16 g_Kh [(size_t)AN * AD], g_Kl [(size_t)AN * AD];
__device__ __nv_bfloat16 g_Vth[(size_t)AD * AN], g_Vtl[(size_t)AD * AN];
__device__ __nv_bfloat16 g_Ph [(size_t)AN * (size_t)AN], g_Pl [(size_t)AN * (size_t)AN];
__device__ float         g_S  [(size_t)AN * (size_t)AN];   // fallback attn scratch

// ---------------------------------------------------------------------------
// helpers
// ---------------------------------------------------------------------------
__device__ __forceinline__ uint32_t smem_u32(const void* p) {
    uint32_t a;
    asm("{ .reg .u64 t; cvta.to.shared.u64 t, %1; cvt.u32.u64 %0, t; }"
        : "=r"(a) : "l"(p));
    return a;
}
__device__ __forceinline__ void cp16(uint32_t dst, const void* src) {
    asm volatile("cp.async.cg.shared.global [%0], [%1], 16;" :: "r"(dst), "l"(src));
}
#define CP_COMMIT() asm volatile("cp.async.commit_group;" ::: "memory")
#define CP_WAIT(N)  asm volatile("cp.async.wait_group %0;" :: "n"(N) : "memory")

__device__ __forceinline__ void ldsm_x4(uint32_t* r, uint32_t addr) {
    asm volatile("ldmatrix.sync.aligned.m8n8.x4.shared.b16 {%0,%1,%2,%3}, [%4];"
                 : "=r"(r[0]), "=r"(r[1]), "=r"(r[2]), "=r"(r[3]) : "r"(addr));
}
__device__ __forceinline__ void ldsm_x2(uint32_t* r, uint32_t addr) {
    asm volatile("ldmatrix.sync.aligned.m8n8.x2.shared.b16 {%0,%1}, [%2];"
                 : "=r"(r[0]), "=r"(r[1]) : "r"(addr));
}
__device__ __forceinline__ void mma16816(float* d, const uint32_t* a, const uint32_t* b) {
    asm volatile(
        "mma.sync.aligned.m16n8k16.row.col.f32.bf16.bf16.f32 "
        "{%0,%1,%2,%3}, {%4,%5,%6,%7}, {%8,%9}, {%0,%1,%2,%3};"
        : "+f"(d[0]), "+f"(d[1]), "+f"(d[2]), "+f"(d[3])
        : "r"(a[0]), "r"(a[1]), "r"(a[2]), "r"(a[3]), "r"(b[0]), "r"(b[1]));
}
__device__ __forceinline__ void split1(float v, __nv_bfloat16& h, __nv_bfloat16& l) {
    h = __float2bfloat16_rn(v);
    l = __float2bfloat16_rn(v - __bfloat162float(h));
}

// ---------------------------------------------------------------------------
// split kernel: fp32 -> (hi, lo) bf16
// ---------------------------------------------------------------------------
__global__ __launch_bounds__(256)
void split_f32(const float* __restrict__ in, __nv_bfloat16* __restrict__ hi,
               __nv_bfloat16* __restrict__ lo, int n4)
{
    int i = blockIdx.x * 256 + threadIdx.x;
    if (i >= n4) return;
    float4 v = *(const float4*)(in + (size_t)i * 4);
    __nv_bfloat16 h0, h1, h2, h3, l0, l1, l2, l3;
    split1(v.x, h0, l0); split1(v.y, h1, l1);
    split1(v.z, h2, l2); split1(v.w, h3, l3);
    *(__nv_bfloat162*)(hi + (size_t)i * 4)     = __nv_bfloat162(h0, h1);
    *(__nv_bfloat162*)(hi + (size_t)i * 4 + 2) = __nv_bfloat162(h2, h3);
    *(__nv_bfloat162*)(lo + (size_t)i * 4)     = __nv_bfloat162(l0, l1);
    *(__nv_bfloat162*)(lo + (size_t)i * 4 + 2) = __nv_bfloat162(l2, l3);
}

// ---------------------------------------------------------------------------
// NT split-bf16 GEMM: C[M,Nn] = (Ah+Al)[M,K] * (Bh+Bl)[Nn,K]^T
// Tile 128x128x32, 256 threads, 2-stage cp.async, warp tile 64x32, 3 passes.
// EPI: 0 = split bf16 out (Chi/Clo), 1 = mask+scale fp32, 2 = fp32
// smem row stride 80B (32 bf16 data + 16B pad): conflict-free ldmatrix.
// ---------------------------------------------------------------------------
#define RS 80                          // smem row stride bytes
#define MATB (128 * RS)                // one matrix (Ah|Al|Bh|Bl) per stage
#define STAGEB (4 * MATB)              // 40960 B
#define SMEM_TOT (2 * STAGEB)          // 81920 B

template <int EPI>
__global__ __launch_bounds__(256)
void hgemm_nt(const __nv_bfloat16* __restrict__ Ah, const __nv_bfloat16* __restrict__ Al,
              const __nv_bfloat16* __restrict__ Bh, const __nv_bfloat16* __restrict__ Bl,
              int M, int Nn, int K,
              float* __restrict__ Cf,
              __nv_bfloat16* __restrict__ Chi, __nv_bfloat16* __restrict__ Clo,
              const int* __restrict__ mask, float scale)
{
    extern __shared__ char smem[];
    const uint32_t sb = smem_u32(smem);
    const int tid = threadIdx.x;
    const int wid = tid >> 5, lid = tid & 31;
    const int mBase = blockIdx.y * 128;
    const int nBase = blockIdx.x * 128;
    const int mW = (wid & 1) * 64;       // warp m offset
    const int nW = (wid >> 1) * 32;      // warp n offset

    // gmem base pointers for this block's tile rows
    const __nv_bfloat16* gA[2] = { Ah + (size_t)mBase * K, Al + (size_t)mBase * K };
    const __nv_bfloat16* gB[2] = { Bh + (size_t)nBase * K, Bl + (size_t)nBase * K };

    float acc[4][4][4];
#pragma unroll
    for (int i = 0; i < 4; i++)
#pragma unroll
        for (int j = 0; j < 4; j++)
#pragma unroll
            for (int v = 0; v < 4; v++) acc[i][j][v] = 0.f;

    const int ntiles = K / 32;

    // ---- async load of one k-tile into stage s ----
    auto load_tile = [&](int kt, int s) {
        const int k0 = kt * 32;
        const uint32_t st = sb + s * STAGEB;
#pragma unroll
        for (int j = 0; j < 2; ++j) {
            int c = tid + j * 256;              // 0..511
            int row = c >> 2, ch = c & 3;
            size_t go = (size_t)row * K + k0 + ch * 8;
            uint32_t so = row * RS + ch * 16;
            cp16(st + 0 * MATB + so, gA[0] + go);
            cp16(st + 1 * MATB + so, gA[1] + go);
            cp16(st + 2 * MATB + so, gB[0] + go);
            cp16(st + 3 * MATB + so, gB[1] + go);
        }
        CP_COMMIT();
    };

    load_tile(0, 0);

    for (int kt = 0; kt < ntiles; ++kt) {
        if (kt + 1 < ntiles) {
            load_tile(kt + 1, (kt + 1) & 1);
            CP_WAIT(1);
        } else {
            CP_WAIT(0);
        }
        __syncthreads();

        const uint32_t st = sb + (kt & 1) * STAGEB;

#pragma unroll
        for (int s = 0; s < 2; ++s) {
            uint32_t ah[4][4], al[4][4], bh[4][2], bl[4][2];
            const uint32_t kb  = s * 32 + ((lid >> 4) * 16);        // A k-byte sel
            const uint32_t kbB = s * 32 + (((lid >> 3) & 1) * 16);  // B k-byte sel
#pragma unroll
            for (int f = 0; f < 4; ++f) {
                uint32_t ra = st + 0 * MATB + (mW + f * 16 + (lid & 15)) * RS + kb;
                ldsm_x4(ah[f], ra);
                ldsm_x4(al[f], ra + MATB);
            }
#pragma unroll
            for (int f = 0; f < 4; ++f) {
                uint32_t rb = st + 2 * MATB + (nW + f * 8 + (lid & 7)) * RS + kbB;
                ldsm_x2(bh[f], rb);
                ldsm_x2(bl[f], rb + MATB);
            }
#pragma unroll
            for (int mf = 0; mf < 4; ++mf)
#pragma unroll
                for (int nf = 0; nf < 4; ++nf) {
                    mma16816(acc[mf][nf], ah[mf], bh[nf]);
                    mma16816(acc[mf][nf], ah[mf], bl[nf]);
                    mma16816(acc[mf][nf], al[mf], bh[nf]);
                }
        }
        __syncthreads();
    }

    // ---- epilogue ----
    const int r0b = mBase + mW + (lid >> 2);
    const int c0b = nBase + nW + (lid & 3) * 2;
#pragma unroll
    for (int mf = 0; mf < 4; ++mf) {
#pragma unroll
        for (int nf = 0; nf < 4; ++nf) {
            const float* d = acc[mf][nf];
#pragma unroll
            for (int h = 0; h < 2; ++h) {           // h=0: rows r, h=1: rows r+8
                int row = r0b + mf * 16 + h * 8;
                int col = c0b + nf * 8;
                size_t o = (size_t)row * Nn + col;
                float v0 = d[h * 2 + 0], v1 = d[h * 2 + 1];
                if (EPI == 0) {
                    __nv_bfloat16 h0, h1, l0, l1;
                    split1(v0, h0, l0); split1(v1, h1, l1);
                    *(__nv_bfloat162*)(Chi + o) = __nv_bfloat162(h0, h1);
                    *(__nv_bfloat162*)(Clo + o) = __nv_bfloat162(l0, l1);
                } else if (EPI == 1) {
                    int2 mv = *(const int2*)(mask + o);
                    float2 w;
                    w.x = mv.x ? -1e9f : v0 * scale;
                    w.y = mv.y ? -1e9f : v1 * scale;
                    *(float2*)(Cf + o) = w;
                } else {
                    *(float2*)(Cf + o) = make_float2(v0, v1);
                }
            }
        }
    }
}

// ---------------------------------------------------------------------------
// Row softmax (in place, fp32) + emit P hi/lo bf16.
// ---------------------------------------------------------------------------
__global__ __launch_bounds__(256)
void softmax_rows(float* __restrict__ S, __nv_bfloat16* __restrict__ Ph,
                  __nv_bfloat16* __restrict__ Pl, int n)
{
    extern __shared__ float row[];
    __shared__ float red[33];

    const int tid = threadIdx.x;
    float* p = S + (size_t)blockIdx.x * n;
    __nv_bfloat16* ph = Ph + (size_t)blockIdx.x * n;
    __nv_bfloat16* pl = Pl + (size_t)blockIdx.x * n;

    float m = -INFINITY;
    for (int i = tid * 4; i < n; i += 1024) {
        float4 v = *(const float4*)(p + i);
        *(float4*)(row + i) = v;
        m = fmaxf(m, fmaxf(fmaxf(v.x, v.y), fmaxf(v.z, v.w)));
    }
#pragma unroll
    for (int o = 16; o; o >>= 1) m = fmaxf(m, __shfl_xor_sync(~0u, m, o));
    if ((tid & 31) == 0) red[tid >> 5] = m;
    __syncthreads();
    if (tid < 32) {
        float v = (tid < 8) ? red[tid] : -INFINITY;
#pragma unroll
        for (int o = 4; o; o >>= 1) v = fmaxf(v, __shfl_xor_sync(~0u, v, o));
        if (tid == 0) red[32] = v;
    }
    __syncthreads();
    m = red[32];

    float s = 0.f;
    for (int i = tid * 4; i < n; i += 1024) {
        float4 v = *(float4*)(row + i);
        v.x = __expf(v.x - m); v.y = __expf(v.y - m);
        v.z = __expf(v.z - m); v.w = __expf(v.w - m);
        s += (v.x + v.y) + (v.z + v.w);
        *(float4*)(row + i) = v;
    }
    __syncthreads();
#pragma unroll
    for (int o = 16; o; o >>= 1) s += __shfl_xor_sync(~0u, s, o);
    if ((tid & 31) == 0) red[tid >> 5] = s;
    __syncthreads();
    if (tid < 32) {
        float v = (tid < 8) ? red[tid] : 0.f;
#pragma unroll
        for (int o = 4; o; o >>= 1) v += __shfl_xor_sync(~0u, v, o);
        if (tid == 0) red[32] = v;
    }
    __syncthreads();
    const float inv = 1.f / red[32];

    for (int i = tid * 4; i < n; i += 1024) {
        float4 v = *(float4*)(row + i);
        v.x *= inv; v.y *= inv; v.z *= inv; v.w *= inv;
        *(float4*)(p + i) = v;
        __nv_bfloat16 h0, h1, h2, h3, l0, l1, l2, l3;
        split1(v.x, h0, l0); split1(v.y, h1, l1);
        split1(v.z, h2, l2); split1(v.w, h3, l3);
        *(__nv_bfloat162*)(ph + i)     = __nv_bfloat162(h0, h1);
        *(__nv_bfloat162*)(ph + i + 2) = __nv_bfloat162(h2, h3);
        *(__nv_bfloat162*)(pl + i)     = __nv_bfloat162(l0, l1);
        *(__nv_bfloat162*)(pl + i + 2) = __nv_bfloat162(l2, l3);
    }
}

// ---------------------------------------------------------------------------
// Launch
// ---------------------------------------------------------------------------
extern "C" void kernel_launch(void* const* d_in, const int* in_sizes, int n_in,
                              void* d_out, int out_size)
{
    const float* x    = (const float*)d_in[0];
    const int*   mask = (const int*)d_in[1];
    const float* Wq   = (const float*)d_in[2];
    const float* Wk   = (const float*)d_in[3];
    const float* Wv   = (const float*)d_in[4];
    float* out = (float*)d_out;

    __nv_bfloat16 *xh, *xl, *Wqh, *Wql, *Wkh, *Wkl, *Wvh, *Wvl;
    __nv_bfloat16 *Qh, *Ql, *Kh, *Kl, *Vth, *Vtl, *Ph, *Pl;
    cudaGetSymbolAddress((void**)&xh,  g_xh);  cudaGetSymbolAddress((void**)&xl,  g_xl);
    cudaGetSymbolAddress((void**)&Wqh, g_Wqh); cudaGetSymbolAddress((void**)&Wql, g_Wql);
    cudaGetSymbolAddress((void**)&Wkh, g_Wkh); cudaGetSymbolAddress((void**)&Wkl, g_Wkl);
    cudaGetSymbolAddress((void**)&Wvh, g_Wvh); cudaGetSymbolAddress((void**)&Wvl, g_Wvl);
    cudaGetSymbolAddress((void**)&Qh,  g_Qh);  cudaGetSymbolAddress((void**)&Ql,  g_Ql);
    cudaGetSymbolAddress((void**)&Kh,  g_Kh);  cudaGetSymbolAddress((void**)&Kl,  g_Kl);
    cudaGetSymbolAddress((void**)&Vth, g_Vth); cudaGetSymbolAddress((void**)&Vtl, g_Vtl);
    cudaGetSymbolAddress((void**)&Ph,  g_Ph);  cudaGetSymbolAddress((void**)&Pl,  g_Pl);

    const size_t nd = (size_t)AN * AD;
    const size_t nn = (size_t)AN * AN;
    float* cntx = out;
    float* attn = out + nd;
    if ((size_t)out_size < nd + nn)
        cudaGetSymbolAddress((void**)&attn, g_S);

    const float scale = 1.0f / sqrtf((float)AD);

    cudaFuncSetAttribute(hgemm_nt<0>, cudaFuncAttributeMaxDynamicSharedMemorySize, SMEM_TOT);
    cudaFuncSetAttribute(hgemm_nt<1>, cudaFuncAttributeMaxDynamicSharedMemorySize, SMEM_TOT);
    cudaFuncSetAttribute(hgemm_nt<2>, cudaFuncAttributeMaxDynamicSharedMemorySize, SMEM_TOT);

    // 1) split inputs
    split_f32<<<(AN * AD / 4 + 255) / 256, 256>>>(x,  xh,  xl,  AN * AD / 4);
    split_f32<<<(AD * AD / 4 + 255) / 256, 256>>>(Wq, Wqh, Wql, AD * AD / 4);
    split_f32<<<(AD * AD / 4 + 255) / 256, 256>>>(Wk, Wkh, Wkl, AD * AD / 4);
    split_f32<<<(AD * AD / 4 + 255) / 256, 256>>>(Wv, Wvh, Wvl, AD * AD / 4);

    // 2) projections (split epilogue)
    dim3 gP(AD / 128, AN / 128);
    hgemm_nt<0><<<gP, 256, SMEM_TOT>>>(xh, xl, Wqh, Wql, AN, AD, AD,
                                       nullptr, Qh, Ql, nullptr, 1.f);
    hgemm_nt<0><<<gP, 256, SMEM_TOT>>>(xh, xl, Wkh, Wkl, AN, AD, AD,
                                       nullptr, Kh, Kl, nullptr, 1.f);
    dim3 gV(AN / 128, AD / 128);
    hgemm_nt<0><<<gV, 256, SMEM_TOT>>>(Wvh, Wvl, xh, xl, AD, AN, AD,
                                       nullptr, Vth, Vtl, nullptr, 1.f);

    // 3) scores (mask epilogue, fp32)
    dim3 gS(AN / 128, AN / 128);
    hgemm_nt<1><<<gS, 256, SMEM_TOT>>>(Qh, Ql, Kh, Kl, AN, AN, AD,
                                       attn, nullptr, nullptr, mask, scale);

    // 4) softmax (+ P hi/lo)
    softmax_rows<<<AN, 256, AN * sizeof(float)>>>(attn, Ph, Pl, AN);

    // 5) context (fp32 epilogue)
    dim3 gC(AD / 128, AN / 128);
    hgemm_nt<2><<<gC, 256, SMEM_TOT>>>(Ph, Pl, Vth, Vtl, AN, AD, AN,
                                       cntx, nullptr, nullptr, nullptr, 1.f);
}